// round 1
// baseline (speedup 1.0000x reference)
#include <cuda_runtime.h>
#include <math.h>

// Problem constants
#define B    512
#define T    365
#define INP  10
#define H    256
#define G3   768
#define OUT  20

// Decomposition: 4 batch groups x 32 column groups = 128 persistent CTAs
#define GB        4
#define GC        32
#define NCTA      (GB * GC)
#define NTHREADS  256
#define MB        128   // batch rows per CTA
#define HC        8     // h-columns per CTA (gate rows = 3*HC = 24)
#define WS        260   // padded smem row stride (floats) -> conflict-free weight LDS.128

// Persistent state (double buffered), scratch via __device__ globals (no allocs).
__device__ float g_h0[2][B * H];
__device__ float g_h1[2][B * H];
__device__ unsigned g_count = 0;
__device__ unsigned g_gen = 0;

__device__ __forceinline__ void grid_sync() {
    __threadfence();          // make this thread's L2 writes visible
    __syncthreads();          // all CTA threads' writes precede thread0's arrival
    if (threadIdx.x == 0) {
        unsigned gen = *(volatile unsigned*)&g_gen;
        if (atomicAdd(&g_count, 1u) == NCTA - 1u) {
            g_count = 0u;
            __threadfence();
            atomicAdd(&g_gen, 1u);
        } else {
            while (*(volatile unsigned*)&g_gen == gen) { }
        }
    }
    __syncthreads();
}

// Accumulate 3 gate dot-products over K=256 for 4 batch rows.
// hin: global fp32 [B][H] read via L2 (__ldcg, coherence across the grid barrier).
// sW : smem, 24 rows (g*8+jc), stride WS.
__device__ __forceinline__ void gemm3(const float* __restrict__ hin, int b0,
                                      const float* __restrict__ sW, int jc,
                                      float* __restrict__ acc /*[12] = [g*4+r]*/) {
    const float4* __restrict__ hp  = reinterpret_cast<const float4*>(hin);
    const float4* __restrict__ w0p = reinterpret_cast<const float4*>(sW + (0 + jc) * WS);
    const float4* __restrict__ w1p = reinterpret_cast<const float4*>(sW + (8 + jc) * WS);
    const float4* __restrict__ w2p = reinterpret_cast<const float4*>(sW + (16 + jc) * WS);
#pragma unroll 4
    for (int k4 = 0; k4 < H / 4; ++k4) {
        float4 w0 = w0p[k4];
        float4 w1 = w1p[k4];
        float4 w2 = w2p[k4];
#pragma unroll
        for (int r = 0; r < 4; ++r) {
            float4 hv = __ldcg(hp + (size_t)(b0 + r) * (H / 4) + k4);
            acc[0 * 4 + r] += hv.x * w0.x + hv.y * w0.y + hv.z * w0.z + hv.w * w0.w;
            acc[1 * 4 + r] += hv.x * w1.x + hv.y * w1.y + hv.z * w1.z + hv.w * w1.w;
            acc[2 * 4 + r] += hv.x * w2.x + hv.y * w2.y + hv.z * w2.z + hv.w * w2.w;
        }
    }
}

__device__ __forceinline__ float sigmoidf_(float v) {
    return 1.0f / (1.0f + expf(-v));
}

__global__ void __launch_bounds__(NTHREADS, 1)
gru_persistent_kernel(const float* __restrict__ x,
                      const float* __restrict__ W_ih0, const float* __restrict__ W_hh0,
                      const float* __restrict__ b_ih0, const float* __restrict__ b_hh0,
                      const float* __restrict__ W_ih1, const float* __restrict__ W_hh1,
                      const float* __restrict__ b_ih1, const float* __restrict__ b_hh1,
                      const float* __restrict__ W_out, const float* __restrict__ b_out,
                      float* __restrict__ out) {
    extern __shared__ float sm[];
    float* sWh0 = sm;                       // 24*WS
    float* sWi1 = sWh0 + 24 * WS;           // 24*WS
    float* sWh1 = sWi1 + 24 * WS;           // 24*WS
    float* sWi0 = sWh1 + 24 * WS;           // 24*12 (padded)
    float* sBi0 = sWi0 + 24 * 12;           // 24
    float* sBh0 = sBi0 + 24;                // 24
    float* sBi1 = sBh0 + 24;                // 24
    float* sBh1 = sBi1 + 24;                // 24

    const int tid = threadIdx.x;
    const int gb  = blockIdx.x >> 5;        // batch group 0..3
    const int gc  = blockIdx.x & 31;        // column group 0..31
    const int c0  = gc * HC;
    const int jc  = tid & 7;                // h-column within CTA
    const int rg  = tid >> 3;               // row group 0..31
    const int b0  = gb * MB + rg * 4;       // first of 4 batch rows
    const int c   = c0 + jc;                // global h column

    // ---- Prologue: weights -> smem (once; resident all 365 steps) ----
    for (int idx = tid; idx < 24 * 256; idx += NTHREADS) {
        int row = idx >> 8, k = idx & 255;
        int g = row >> 3, j = row & 7;
        int grow = g * H + c0 + j;
        sWh0[row * WS + k] = W_hh0[grow * H + k];
        sWi1[row * WS + k] = W_ih1[grow * H + k];
        sWh1[row * WS + k] = W_hh1[grow * H + k];
    }
    for (int idx = tid; idx < 24 * INP; idx += NTHREADS) {
        int row = idx / INP, i = idx - row * INP;
        int g = row >> 3, j = row & 7;
        int grow = g * H + c0 + j;
        sWi0[row * 12 + i] = W_ih0[grow * INP + i];
    }
    if (tid < 24) {
        int g = tid >> 3, j = tid & 7;
        int grow = g * H + c0 + j;
        sBi0[tid] = b_ih0[grow];
        sBh0[tid] = b_hh0[grow];
        sBi1[tid] = b_ih1[grow];
        sBh1[tid] = b_hh1[grow];
    }

    // Zero initial hidden state (buffers read at t=0). Every launch (determinism).
    for (int idx = blockIdx.x * NTHREADS + tid; idx < B * H; idx += NCTA * NTHREADS) {
        __stcg(&g_h0[0][idx], 0.0f);
        __stcg(&g_h1[0][idx], 0.0f);
    }
    __syncthreads();
    grid_sync();

    // ---- Main sequential loop ----
    for (int t = 0; t < T; ++t) {
        const float* h0r = g_h0[t & 1];
        float*       h0w = g_h0[(t & 1) ^ 1];
        const float* h1r = g_h1[t & 1];
        float*       h1w = g_h1[(t & 1) ^ 1];

        float ai[12], ah[12];

        // ===== Layer 0: gates = x_t @ W_ih0^T + b_ih0  |  h0 @ W_hh0^T + b_hh0 =====
#pragma unroll
        for (int g = 0; g < 3; ++g)
#pragma unroll
            for (int r = 0; r < 4; ++r) {
                ai[g * 4 + r] = sBi0[g * 8 + jc];
                ah[g * 4 + r] = sBh0[g * 8 + jc];
            }

#pragma unroll
        for (int r = 0; r < 4; ++r) {
            const float* xr = x + ((size_t)(b0 + r) * T + t) * INP;
#pragma unroll
            for (int i = 0; i < INP; ++i) {
                float xv = __ldg(&xr[i]);
#pragma unroll
                for (int g = 0; g < 3; ++g)
                    ai[g * 4 + r] += xv * sWi0[(g * 8 + jc) * 12 + i];
            }
        }
        gemm3(h0r, b0, sWh0, jc, ah);

#pragma unroll
        for (int r = 0; r < 4; ++r) {
            float rr = sigmoidf_(ai[0 * 4 + r] + ah[0 * 4 + r]);
            float zz = sigmoidf_(ai[1 * 4 + r] + ah[1 * 4 + r]);
            float nn = tanhf(ai[2 * 4 + r] + rr * ah[2 * 4 + r]);
            float hold = __ldcg(&h0r[(size_t)(b0 + r) * H + c]);
            __stcg(&h0w[(size_t)(b0 + r) * H + c], (1.0f - zz) * nn + zz * hold);
        }

        grid_sync();   // h0_t complete, visible in L2

        // ===== Layer 1: gates = h0_t @ W_ih1^T + b_ih1  |  h1 @ W_hh1^T + b_hh1 =====
#pragma unroll
        for (int g = 0; g < 3; ++g)
#pragma unroll
            for (int r = 0; r < 4; ++r) {
                ai[g * 4 + r] = sBi1[g * 8 + jc];
                ah[g * 4 + r] = sBh1[g * 8 + jc];
            }
        gemm3(h0w, b0, sWi1, jc, ai);
        gemm3(h1r, b0, sWh1, jc, ah);

#pragma unroll
        for (int r = 0; r < 4; ++r) {
            float rr = sigmoidf_(ai[0 * 4 + r] + ah[0 * 4 + r]);
            float zz = sigmoidf_(ai[1 * 4 + r] + ah[1 * 4 + r]);
            float nn = tanhf(ai[2 * 4 + r] + rr * ah[2 * 4 + r]);
            float hold = __ldcg(&h1r[(size_t)(b0 + r) * H + c]);
            __stcg(&h1w[(size_t)(b0 + r) * H + c], (1.0f - zz) * nn + zz * hold);
        }

        grid_sync();   // h1_t complete
    }

    // ---- Epilogue: logits + softmax, one warp per batch row ----
    const float* hfin = g_h1[T & 1];   // final h1 buffer
    int gw = blockIdx.x * (NTHREADS / 32) + (tid >> 5);
    int lane = tid & 31;
    if (gw < B) {
        const float* hrow = hfin + (size_t)gw * H;
        float hk[8];
#pragma unroll
        for (int j2 = 0; j2 < 8; ++j2) hk[j2] = __ldcg(&hrow[lane + 32 * j2]);

        float logits[OUT];
#pragma unroll
        for (int o = 0; o < OUT; ++o) {
            float p = 0.0f;
#pragma unroll
            for (int j2 = 0; j2 < 8; ++j2)
                p += hk[j2] * __ldg(&W_out[o * H + lane + 32 * j2]);
#pragma unroll
            for (int s = 16; s > 0; s >>= 1)
                p += __shfl_xor_sync(0xffffffffu, p, s);
            logits[o] = p + __ldg(&b_out[o]);
        }
        float mx = logits[0];
#pragma unroll
        for (int o = 1; o < OUT; ++o) mx = fmaxf(mx, logits[o]);
        float sum = 0.0f;
#pragma unroll
        for (int o = 0; o < OUT; ++o) { logits[o] = expf(logits[o] - mx); sum += logits[o]; }
        float inv = 1.0f / sum;
        if (lane == 0) {
#pragma unroll
            for (int o = 0; o < OUT; ++o)
                out[(size_t)gw * OUT + o] = logits[o] * inv;
        }
    }
}

extern "C" void kernel_launch(void* const* d_in, const int* in_sizes, int n_in,
                              void* d_out, int out_size) {
    const float* x      = (const float*)d_in[0];
    // d_in[1] = times (unused), d_in[2] = interpolation_method (unused)
    const float* W_ih0  = (const float*)d_in[3];
    const float* W_hh0  = (const float*)d_in[4];
    const float* b_ih0  = (const float*)d_in[5];
    const float* b_hh0  = (const float*)d_in[6];
    const float* W_ih1  = (const float*)d_in[7];
    const float* W_hh1  = (const float*)d_in[8];
    const float* b_ih1  = (const float*)d_in[9];
    const float* b_hh1  = (const float*)d_in[10];
    const float* W_out  = (const float*)d_in[11];
    const float* b_out  = (const float*)d_in[12];
    float* out = (float*)d_out;

    const size_t smem_bytes = (size_t)(3 * 24 * WS + 24 * 12 + 4 * 24) * sizeof(float); // 76,416 B
    cudaFuncSetAttribute(gru_persistent_kernel,
                         cudaFuncAttributeMaxDynamicSharedMemorySize, (int)smem_bytes);

    gru_persistent_kernel<<<NCTA, NTHREADS, smem_bytes>>>(
        x, W_ih0, W_hh0, b_ih0, b_hh0,
        W_ih1, W_hh1, b_ih1, b_hh1,
        W_out, b_out, out);
}